// round 16
// baseline (speedup 1.0000x reference)
#include <cuda_runtime.h>
#include <cstdint>

// Problem shape (fixed by the reference)
#define BATCH 32
#define CHAN  17
#define HW    65536                       // 256*256
#define CHW   (CHAN * HW)                 // 1114112 floats per image
#define PIX_PER_CHUNK 512
#define CHUNKS_PER_IMG (HW / PIX_PER_CHUNK)   // 128
#define NCHUNKS (BATCH * CHUNKS_PER_IMG)      // 4096
#define THREADS 256
#define NBLOCKS 152                       // one persistent block per SM (GB300: 152 SMs)

#define SEG_BYTES (PIX_PER_CHUNK * 4)             // 2048 B per channel segment
#define STAGE_TENSOR_BYTES (CHAN * SEG_BYTES)     // 34816 B (one tensor, one chunk)
#define STAGE_BYTES (2 * STAGE_TENSOR_BYTES)      // 69632 B (target + input)
#define NSTAGES 2
#define SMEM_STAGE_OFF 128                        // mbarriers live below this
#define SMEM_TOTAL (SMEM_STAGE_OFF + NSTAGES * STAGE_BYTES)   // 139392 B

// Global scratch accumulators (no cudaMalloc allowed). Zero-initialized at
// module load; the finalizing block resets them so graph replays see zeros.
__device__ double             g_sum1;
__device__ double             g_sum2;
__device__ unsigned long long g_cnt1;
__device__ unsigned long long g_cnt2;
__device__ unsigned int       g_done;

__device__ __forceinline__ uint32_t smem_u32(const void* p) {
    uint32_t a;
    asm("{ .reg .u64 t; cvta.to.shared.u64 t, %1; cvt.u32.u64 %0, t; }" : "=r"(a) : "l"(p));
    return a;
}

__device__ __forceinline__ void mbar_init(uint32_t mbar, uint32_t count) {
    asm volatile("mbarrier.init.shared.b64 [%0], %1;" :: "r"(mbar), "r"(count) : "memory");
}
__device__ __forceinline__ void mbar_expect_tx(uint32_t mbar, uint32_t bytes) {
    asm volatile("mbarrier.arrive.expect_tx.shared.b64 _, [%0], %1;"
                 :: "r"(mbar), "r"(bytes) : "memory");
}
__device__ __forceinline__ void mbar_wait(uint32_t mbar, uint32_t phase) {
    asm volatile(
        "{\n\t.reg .pred P;\n"
        "W_%=:\n\t"
        "mbarrier.try_wait.parity.acquire.cta.shared::cta.b64 P, [%0], %1, 0x989680;\n\t"
        "@P bra D_%=;\n\t"
        "bra W_%=;\n"
        "D_%=:\n\t}"
        :: "r"(mbar), "r"(phase) : "memory");
}
// 1D bulk async copy global -> shared, completion via mbarrier tx bytes.
__device__ __forceinline__ void bulk_g2s(uint32_t dst_smem, const void* src, uint32_t bytes,
                                         uint32_t mbar) {
    asm volatile(
        "cp.async.bulk.shared::cluster.global.mbarrier::complete_tx::bytes [%0], [%1], %2, [%3];"
        :: "r"(dst_smem), "l"(src), "r"(bytes), "r"(mbar) : "memory");
}

__inline__ __device__ float warpReduceF(float v) {
#pragma unroll
    for (int o = 16; o > 0; o >>= 1) v += __shfl_down_sync(0xffffffffu, v, o);
    return v;
}
__inline__ __device__ int warpReduceI(int v) {
#pragma unroll
    for (int o = 16; o > 0; o >>= 1) v += __shfl_down_sync(0xffffffffu, v, o);
    return v;
}

__global__ void __launch_bounds__(THREADS, 1)
heatloss_bulk_kernel(const float* __restrict__ inp, const float* __restrict__ tgt,
                     float* __restrict__ out) {
    extern __shared__ char smem[];
    const uint32_t smem_base = smem_u32(smem);
    const uint32_t mbar0 = smem_base;          // full[0] at +0, full[1] at +8
    const int tid = threadIdx.x;

    if (tid == 0) {
        mbar_init(mbar0 + 0, 1);
        mbar_init(mbar0 + 8, 1);
        asm volatile("fence.proxy.async.shared::cta;" ::: "memory");
    }
    __syncthreads();

    // Chunks for this block: blockIdx.x, blockIdx.x + 152, ...
    const unsigned bid = blockIdx.x;
    const unsigned local_n = (NCHUNKS - bid + (NBLOCKS - 1)) / NBLOCKS;

    // Producer: issue chunk 'l' into stage s = l&1.
    auto issue = [&](unsigned l, unsigned s) {
        const unsigned chunk = bid + l * NBLOCKS;
        const unsigned b = chunk >> 7;            // / CHUNKS_PER_IMG
        const unsigned j = chunk & 127;           // % CHUNKS_PER_IMG
        const float* tsrc = tgt + (size_t)b * CHW + (size_t)j * PIX_PER_CHUNK;
        const float* isrc = inp + (size_t)b * CHW + (size_t)j * PIX_PER_CHUNK;
        const uint32_t dT = smem_base + SMEM_STAGE_OFF + s * STAGE_BYTES;
        const uint32_t dI = dT + STAGE_TENSOR_BYTES;
        const uint32_t mb = mbar0 + 8u * s;
        mbar_expect_tx(mb, STAGE_BYTES);
#pragma unroll
        for (int c = 0; c < CHAN; ++c) {
            bulk_g2s(dT + c * SEG_BYTES, tsrc + (size_t)c * HW, SEG_BYTES, mb);
            bulk_g2s(dI + c * SEG_BYTES, isrc + (size_t)c * HW, SEG_BYTES, mb);
        }
    };

    if (tid == 0) {
        if (local_n > 0) issue(0, 0);
        if (local_n > 1) issue(1, 1);
    }

    // Thread-accumulated partials
    float s1 = 0.f, s2 = 0.f;
    int   c1 = 0,   c2 = 0;
    int ph0 = 0, ph1 = 0;   // per-stage wait parity

    for (unsigned l = 0; l < local_n; ++l) {
        const unsigned s = l & 1u;
        if (s == 0) { mbar_wait(mbar0 + 0, ph0); ph0 ^= 1; }
        else        { mbar_wait(mbar0 + 8, ph1); ph1 ^= 1; }

        // Consume: 512 pixels, 2 per thread, 17 channels from smem.
        const char* sb = smem + SMEM_STAGE_OFF + s * STAGE_BYTES;
        const float2* tT = reinterpret_cast<const float2*>(sb);
        const float2* tI = reinterpret_cast<const float2*>(sb + STAGE_TENSOR_BYTES);

        float ps0 = 0.f, ps1 = 0.f;
        unsigned anym = 0u;
#pragma unroll
        for (int c = 0; c < CHAN; ++c) {
            const float2 tv = tT[c * (PIX_PER_CHUNK / 2) + tid];
            const float2 iv = tI[c * (PIX_PER_CHUNK / 2) + tid];
            float d0 = fabsf(iv.x - tv.x);
            float d1 = fabsf(iv.y - tv.y);
            ps0 += d0; ps1 += d1;
            if (tv.x > 0.f) { s1 += d0; ++c1; anym |= 1u; }
            if (tv.y > 0.f) { s1 += d1; ++c1; anym |= 2u; }
        }
        if (anym & 1u) { s2 += ps0; ++c2; }
        if (anym & 2u) { s2 += ps1; ++c2; }

        __syncthreads();                   // everyone done reading stage s
        if (tid == 0 && l + 2 < local_n) issue(l + 2, s);
    }

    // Warp reduce
    s1 = warpReduceF(s1);
    s2 = warpReduceF(s2);
    c1 = warpReduceI(c1);
    c2 = warpReduceI(c2);

    // Block reduce (8 warps)
    __shared__ float sh_s1[8], sh_s2[8];
    __shared__ int   sh_c1[8], sh_c2[8];
    const int lane = tid & 31;
    const int wid  = tid >> 5;
    if (lane == 0) { sh_s1[wid] = s1; sh_s2[wid] = s2; sh_c1[wid] = c1; sh_c2[wid] = c2; }
    __syncthreads();

    __shared__ bool is_last;
    if (wid == 0) {
        s1 = (lane < 8) ? sh_s1[lane] : 0.f;
        s2 = (lane < 8) ? sh_s2[lane] : 0.f;
        c1 = (lane < 8) ? sh_c1[lane] : 0;
        c2 = (lane < 8) ? sh_c2[lane] : 0;
#pragma unroll
        for (int o = 4; o > 0; o >>= 1) {
            s1 += __shfl_down_sync(0xffffffffu, s1, o);
            s2 += __shfl_down_sync(0xffffffffu, s2, o);
            c1 += __shfl_down_sync(0xffffffffu, c1, o);
            c2 += __shfl_down_sync(0xffffffffu, c2, o);
        }
        if (lane == 0) {
            atomicAdd(&g_sum1, (double)s1);
            atomicAdd(&g_sum2, (double)s2);
            atomicAdd(&g_cnt1, (unsigned long long)c1);
            atomicAdd(&g_cnt2, (unsigned long long)c2);
            __threadfence();
            unsigned prev = atomicAdd(&g_done, 1u);
            is_last = (prev == (unsigned)(NBLOCKS - 1));
        }
    }
    __syncthreads();

    if (is_last && tid == 0) {
        double mean1 = g_sum1 / (double)g_cnt1;
        double mean2 = g_sum2 / ((double)g_cnt2 * (double)CHAN);
        out[0] = (float)((mean1 + mean2) * 0.5);
        g_sum1 = 0.0;
        g_sum2 = 0.0;
        g_cnt1 = 0ull;
        g_cnt2 = 0ull;
        __threadfence();
        g_done = 0u;
    }
}

extern "C" void kernel_launch(void* const* d_in, const int* in_sizes, int n_in,
                              void* d_out, int out_size) {
    const float* inp = (const float*)d_in[0];
    const float* tgt = (const float*)d_in[1];
    float* out = (float*)d_out;

    // Attribute set (not an allocation; idempotent, capture-safe).
    cudaFuncSetAttribute(heatloss_bulk_kernel,
                         cudaFuncAttributeMaxDynamicSharedMemorySize, SMEM_TOTAL);
    heatloss_bulk_kernel<<<NBLOCKS, THREADS, SMEM_TOTAL>>>(inp, tgt, out);
}

// round 17
// speedup vs baseline: 1.0288x; 1.0288x over previous
#include <cuda_runtime.h>
#include <cstdint>

// Problem shape (fixed by the reference)
#define BATCH 32
#define CHAN  17
#define HDIM  256
#define WDIM  256
#define HW        (HDIM * WDIM)          // 65536
#define CHW       (CHAN * HW)            // 1114112
#define NPIX      (BATCH * HW)           // 2097152 pixels (b,h,w)
#define QUADS_PER_IMG (HW / 4)           // 16384
#define NQUADS    (NPIX / 4)             // 524288 = 2^19
#define THREADS   256
// 512 blocks x 256 threads = 131072 threads -> exactly 4 quads per thread.
// Equal bytes per block => with a globally-shared DRAM bottleneck all blocks
// finish near-simultaneously (no ragged tail).
#define NBLOCKS   512
#define ITERS     (NQUADS / (NBLOCKS * THREADS))   // 4, exact

// Global scratch accumulators (no cudaMalloc allowed).
// Zero-initialized at module load; the finalizing block resets them to zero
// before kernel exit, so every (graph-replayed) launch sees zeros.
__device__ double             g_sum1;    // sum of diff where target>0
__device__ double             g_sum2;    // sum of channel-summed diff where any-channel>0
__device__ unsigned long long g_cnt1;    // count of target>0 elements
__device__ unsigned long long g_cnt2;    // count of pixels with any-channel>0
__device__ unsigned int       g_done;    // completed-block counter

__inline__ __device__ float warpReduceF(float v) {
#pragma unroll
    for (int o = 16; o > 0; o >>= 1) v += __shfl_down_sync(0xffffffffu, v, o);
    return v;
}
__inline__ __device__ int warpReduceI(int v) {
#pragma unroll
    for (int o = 16; o > 0; o >>= 1) v += __shfl_down_sync(0xffffffffu, v, o);
    return v;
}

__global__ void __launch_bounds__(THREADS, 4)
heatloss_fused_kernel(const float* __restrict__ inp, const float* __restrict__ tgt,
                      float* __restrict__ out) {
    const unsigned stride = NBLOCKS * THREADS;            // 131072
    const unsigned t0     = blockIdx.x * THREADS + threadIdx.x;

    // Thread-accumulated partials across the 4 iterations
    float s1 = 0.f;   // m1-masked diff sum
    float s2 = 0.f;   // m2-masked (channel-summed) diff sum
    int   c1 = 0;     // m1 count (elements)
    int   c2 = 0;     // m2 count (pixels)

#pragma unroll 1
    for (int it = 0; it < ITERS; ++it) {
        const unsigned tid  = t0 + (unsigned)it * stride;
        const unsigned b    = tid / QUADS_PER_IMG;        // image index
        const unsigned quad = tid % QUADS_PER_IMG;        // quad-of-pixels within image

        const float4* ip = reinterpret_cast<const float4*>(inp + (size_t)b * CHW) + quad;
        const float4* tp = reinterpret_cast<const float4*>(tgt + (size_t)b * CHW) + quad;

        float psum0 = 0.f, psum1 = 0.f, psum2 = 0.f, psum3 = 0.f;
        unsigned anym = 0u;   // bit k = pixel k has some channel with target>0

        const unsigned cstride = HW / 4;   // float4 stride between channels
#pragma unroll
        for (int c = 0; c < CHAN; ++c) {
            // Streaming loads (zero reuse): evict-first in L1/L2.
            const float4 t = __ldcs(tp + (size_t)c * cstride);
            const float4 v = __ldcs(ip + (size_t)c * cstride);

            float d0 = fabsf(v.x - t.x);
            float d1 = fabsf(v.y - t.y);
            float d2 = fabsf(v.z - t.z);
            float d3 = fabsf(v.w - t.w);

            psum0 += d0; psum1 += d1; psum2 += d2; psum3 += d3;

            if (t.x > 0.f) { s1 += d0; ++c1; anym |= 1u; }
            if (t.y > 0.f) { s1 += d1; ++c1; anym |= 2u; }
            if (t.z > 0.f) { s1 += d2; ++c1; anym |= 4u; }
            if (t.w > 0.f) { s1 += d3; ++c1; anym |= 8u; }
        }

        if (anym & 1u) { s2 += psum0; ++c2; }
        if (anym & 2u) { s2 += psum1; ++c2; }
        if (anym & 4u) { s2 += psum2; ++c2; }
        if (anym & 8u) { s2 += psum3; ++c2; }
    }

    // Warp reduce
    s1 = warpReduceF(s1);
    s2 = warpReduceF(s2);
    c1 = warpReduceI(c1);
    c2 = warpReduceI(c2);

    // Block reduce via shared memory (8 warps)
    __shared__ float sh_s1[8], sh_s2[8];
    __shared__ int   sh_c1[8], sh_c2[8];
    const int lane = threadIdx.x & 31;
    const int wid  = threadIdx.x >> 5;
    if (lane == 0) { sh_s1[wid] = s1; sh_s2[wid] = s2; sh_c1[wid] = c1; sh_c2[wid] = c2; }
    __syncthreads();

    __shared__ bool is_last;
    if (wid == 0) {
        s1 = (lane < 8) ? sh_s1[lane] : 0.f;
        s2 = (lane < 8) ? sh_s2[lane] : 0.f;
        c1 = (lane < 8) ? sh_c1[lane] : 0;
        c2 = (lane < 8) ? sh_c2[lane] : 0;
#pragma unroll
        for (int o = 4; o > 0; o >>= 1) {
            s1 += __shfl_down_sync(0xffffffffu, s1, o);
            s2 += __shfl_down_sync(0xffffffffu, s2, o);
            c1 += __shfl_down_sync(0xffffffffu, c1, o);
            c2 += __shfl_down_sync(0xffffffffu, c2, o);
        }
        if (lane == 0) {
            atomicAdd(&g_sum1, (double)s1);
            atomicAdd(&g_sum2, (double)s2);
            atomicAdd(&g_cnt1, (unsigned long long)c1);
            atomicAdd(&g_cnt2, (unsigned long long)c2);
            // Make our accumulator contributions visible before signalling done.
            __threadfence();
            unsigned prev = atomicAdd(&g_done, 1u);
            is_last = (prev == (unsigned)(NBLOCKS - 1));
        }
    }
    __syncthreads();

    // The last block to finish finalizes the result and resets state so the
    // next launch (graph replay) starts from zeros again.
    if (is_last && threadIdx.x == 0) {
        double mean1 = g_sum1 / (double)g_cnt1;
        double mean2 = g_sum2 / ((double)g_cnt2 * (double)CHAN);
        out[0] = (float)((mean1 + mean2) * 0.5);
        g_sum1 = 0.0;
        g_sum2 = 0.0;
        g_cnt1 = 0ull;
        g_cnt2 = 0ull;
        __threadfence();
        g_done = 0u;
    }
}

extern "C" void kernel_launch(void* const* d_in, const int* in_sizes, int n_in,
                              void* d_out, int out_size) {
    const float* inp = (const float*)d_in[0];
    const float* tgt = (const float*)d_in[1];
    float* out = (float*)d_out;

    heatloss_fused_kernel<<<NBLOCKS, THREADS>>>(inp, tgt, out);
}